// round 6
// baseline (speedup 1.0000x reference)
#include <cuda_runtime.h>

#define T_DIM 512
#define B_DIM 256
#define N_DIM 128
#define BN    (B_DIM * N_DIM)
#define NCHUNK 128
#define TCHUNK (T_DIM / NCHUNK)
#define NCTA  (B_DIM / 2)            /* 128 forward CTAs */

#define LOGC_F 5.545177444479562f    /* ln 256 */
#define LOGC_D 5.545177444479562

__device__ float g_score[B_DIM];
__device__ float g_logZ[B_DIM];
__device__ int   g_len[B_DIM];
__device__ float g_part_s[NCHUNK * B_DIM];
__device__ int   g_part_c[NCHUNK * B_DIM];
__device__ int2  g_sched[NCTA];
__device__ unsigned int g_done;      /* zero-init; self-resetting */

// ---------------- f32x2 helpers (packed dual fp32 FMA, sm_100+) -------------
__device__ __forceinline__ unsigned long long pack2(float lo, float hi) {
    unsigned long long u;
    asm("mov.b64 %0, {%1,%2};" : "=l"(u) : "f"(lo), "f"(hi));
    return u;
}
__device__ __forceinline__ void unpack2(unsigned long long u, float& lo, float& hi) {
    asm("mov.b64 {%0,%1}, %2;" : "=f"(lo), "=f"(hi) : "l"(u));
}
__device__ __forceinline__ void ffma2(unsigned long long& d,
                                      unsigned long long a, unsigned long long b) {
    asm("fma.rn.f32x2 %0, %1, %2, %0;" : "+l"(d) : "l"(a), "l"(b));
}

// ---------------------------------------------------------------------------
// A1: coalesced partial gold-path score + count per t-chunk. thread = b.
// ---------------------------------------------------------------------------
__global__ void scoreA1(const float* __restrict__ emit,
                        const int*   __restrict__ target,
                        const int*   __restrict__ mask,
                        const float* __restrict__ trans) {
    const int b = threadIdx.x;
    const int c = blockIdx.x;
    const int t0 = c * TCHUNK;
    float s = 0.f; int cnt = 0;
    #pragma unroll
    for (int t = t0; t < t0 + TCHUNK; ++t) {
        if (mask[t * B_DIM + b] != 0) {
            int tg = target[t * B_DIM + b];
            float v = emit[(size_t)t * BN + b * N_DIM + tg];
            if (t > 0) {
                int tp = target[(t - 1) * B_DIM + b];
                v += trans[tp * N_DIM + tg];
            }
            s += v; cnt += 1;
        }
    }
    g_part_s[c * B_DIM + b] = s;
    g_part_c[c * B_DIM + b] = cnt;
}

// ---------------------------------------------------------------------------
// A2: combine partials + bonuses; bitonic sort by length; pairing schedule
// (longest with shortest -> per-CTA total steps ~equal).
// ---------------------------------------------------------------------------
__global__ void scoreA2(const int*   __restrict__ target,
                        const float* __restrict__ strans,
                        const float* __restrict__ etrans) {
    __shared__ int key[B_DIM];
    const int b = threadIdx.x;
    float s = 0.f; int cnt = 0;
    for (int c = 0; c < NCHUNK; ++c) {
        s   += g_part_s[c * B_DIM + b];
        cnt += g_part_c[c * B_DIM + b];
    }
    s += strans[target[b]];
    s += etrans[target[(cnt - 1) * B_DIM + b]];
    g_score[b] = s;
    g_len[b]   = cnt;
    key[b] = (cnt << 9) | b;
    __syncthreads();

    for (int k = 2; k <= B_DIM; k <<= 1) {
        for (int jj = k >> 1; jj > 0; jj >>= 1) {
            int p = b ^ jj;
            if (p > b) {
                int a0 = key[b], a1 = key[p];
                bool asc = ((b & k) == 0);
                if ((a0 > a1) == asc) { key[b] = a1; key[p] = a0; }
            }
            __syncthreads();
        }
    }
    if (b < NCTA)
        g_sched[b] = make_int2(key[B_DIM - 1 - b] & 511, key[b] & 511);
}

// ---------------------------------------------------------------------------
// Forward kernel, MEET-IN-THE-MIDDLE. 128 CTAs x 256 threads.
// chain 0 (threads 0-127):   forward half,  alpha_t = (A^T alpha) . e^{e_t}/256
// chain 1 (threads 128-255): backward half, beta_{t-1} = A (e^{e_t}/256 . beta)
// Both chains ~ (len-1)/2 steps, run concurrently (per-chain named barriers),
// meet at m = (len-1)>>1:  z = sum_j alpha_m[j] * beta_m[j].
// E column (fwd) / row (bwd) in 128 regs as f32x2 pairs; one bar per step;
// renorm every 16 steps; time loop unrolled x4 (static ping-pong, no local mem).
// Final (logZ - score)/B fused via last-CTA pattern.
// ---------------------------------------------------------------------------
__global__ void __launch_bounds__(256, 1)
forward_kernel(const float* __restrict__ emit,
               const float* __restrict__ trans,
               const float* __restrict__ strans,
               const float* __restrict__ etrans,
               float* __restrict__ out) {
    __shared__ __align__(16) float pbuf[2][2][N_DIM];
    __shared__ float  wsum[8];
    __shared__ float  accb_sh;
    __shared__ int    sflag;
    __shared__ double shd[256];

    const int tid   = threadIdx.x;
    const int lane  = tid & 31;
    const int chain = tid >> 7;
    const int j     = tid & 127;
    const int barid = 1 + chain;
    const int wslot = chain * 4 + ((tid >> 5) & 3);
    const int wbase = chain * 4;
    const int2 sc   = g_sched[blockIdx.x];

    // E pairs in registers.
    // fwd (chain 0): over source i for my column j:  (e^{A[2m][j]}, e^{A[2m+1][j]})
    // bwd (chain 1): over source k for my row    j:  (e^{A[j][2m]}, e^{A[j][2m+1]})
    unsigned long long E2[64];
    if (chain == 0) {
        #pragma unroll
        for (int m = 0; m < 64; ++m)
            E2[m] = pack2(__expf(trans[(2 * m) * N_DIM + j]),
                          __expf(trans[(2 * m + 1) * N_DIM + j]));
    } else {
        const float* tr = trans + j * N_DIM;
        #pragma unroll
        for (int m = 0; m < 64; ++m)
            E2[m] = pack2(__expf(tr[2 * m]), __expf(tr[2 * m + 1]));
    }
    const float etr = __expf(etrans[j]);

    float* pb0 = pbuf[chain][0];
    float* pb1 = pbuf[chain][1];

    #define STEP(EE, PR, PW, TT) do {                                        \
        float ee = (EE);                                                     \
        const ulonglong2* pu = (const ulonglong2*)(PR);                      \
        unsigned long long a0 = 0ull, a1 = 0ull, a2 = 0ull, a3 = 0ull;       \
        _Pragma("unroll")                                                    \
        for (int k = 0; k < 32; k += 2) {                                    \
            ulonglong2 x = pu[k];                                            \
            ulonglong2 y = pu[k + 1];                                        \
            ffma2(a0, x.x, E2[2 * k]);                                       \
            ffma2(a1, x.y, E2[2 * k + 1]);                                   \
            ffma2(a2, y.x, E2[2 * k + 2]);                                   \
            ffma2(a3, y.y, E2[2 * k + 3]);                                   \
        }                                                                    \
        float f0, f1, f2, f3, f4, f5, f6, f7;                                \
        unpack2(a0, f0, f1); unpack2(a1, f2, f3);                            \
        unpack2(a2, f4, f5); unpack2(a3, f6, f7);                            \
        v = (((f0 + f1) + (f2 + f3)) + ((f4 + f5) + (f6 + f7))) * ee;        \
        if (((TT) & 15) == 0) {                                              \
            float r = v;                                                     \
            _Pragma("unroll")                                                \
            for (int o = 16; o; o >>= 1)                                     \
                r += __shfl_xor_sync(0xffffffffu, r, o);                     \
            if (lane == 0) wsum[wslot] = r;                                  \
            asm volatile("bar.sync %0, 128;" :: "r"(barid) : "memory");      \
            float ss = wsum[wbase] + wsum[wbase + 1]                         \
                     + wsum[wbase + 2] + wsum[wbase + 3];                    \
            v *= (1.f / ss);                                                 \
            acc_log += __logf(ss);                                           \
        }                                                                    \
        (PW)[j] = v;                                                         \
        asm volatile("bar.sync %0, 128;" :: "r"(barid) : "memory");          \
    } while (0)

    #pragma unroll 1
    for (int pi = 0; pi < 2; ++pi) {
        const int b     = pi ? sc.y : sc.x;
        const int len   = g_len[b];
        const int m     = (len - 1) >> 1;       // fwd steps
        const int nbwd  = (len - 1) - m;        // bwd steps
        const float* eb = emit + b * N_DIM + j;

        float acc_log = 0.f;
        float v;

        if (chain == 0) {
            // ---------------- forward half: steps t = 1..m ----------------
            v = __expf(strans[j] + eb[0]);
            if (m > 0) {
                pb0[j] = v;
                // emit index ring: t ascending from 1 (clamped to len-1: safe reads)
                const int lm1 = len - 1;
                #define LDEF(TT) eb[(size_t)(((TT) < lm1) ? (TT) : lm1) * BN]
                float e0 = LDEF(1), e1 = LDEF(2), e2 = LDEF(3), e3 = LDEF(4);
                asm volatile("bar.sync %0, 128;" :: "r"(barid) : "memory");
                int t = 1;
                #pragma unroll 1
                for (; t + 3 <= m; t += 4) {
                    float n0 = LDEF(t + 4), n1 = LDEF(t + 5),
                          n2 = LDEF(t + 6), n3 = LDEF(t + 7);
                    STEP(__expf(e0 - LOGC_F), pb0, pb1, t);
                    STEP(__expf(e1 - LOGC_F), pb1, pb0, t + 1);
                    STEP(__expf(e2 - LOGC_F), pb0, pb1, t + 2);
                    STEP(__expf(e3 - LOGC_F), pb1, pb0, t + 3);
                    e0 = n0; e1 = n1; e2 = n2; e3 = n3;
                }
                if (t <= m) { STEP(__expf(e0 - LOGC_F), pb0, pb1, t); ++t; }
                if (t <= m) { STEP(__expf(e1 - LOGC_F), pb1, pb0, t); ++t; }
                if (t <= m) { STEP(__expf(e2 - LOGC_F), pb0, pb1, t); }
                #undef LDEF
            }
            // v = alpha_m (scaled); acc_log = acc_f
        } else {
            // ---------------- backward half: nbwd steps --------------------
            if (nbwd == 0) {
                v = etr;                         // beta_m = e^{etrans}
            } else {
                // init w_{len-1} = e^{emit[len-1] + etrans - ln256}
                v = __expf(eb[(size_t)(len - 1) * BN] + etrans[j] - LOGC_F);
                pb0[j] = v;
                // step s consumes emit[len-2-s] for s < nbwd-1; last step ee=1
                #define LDEB(SS) eb[(size_t)(((len - 2 - (SS)) > 0) ? (len - 2 - (SS)) : 0) * BN]
                float e0 = LDEB(0), e1 = LDEB(1), e2 = LDEB(2), e3 = LDEB(3);
                asm volatile("bar.sync %0, 128;" :: "r"(barid) : "memory");
                const int last = nbwd - 1;
                int s = 0;
                #pragma unroll 1
                for (; s + 3 < nbwd; s += 4) {
                    float n0 = LDEB(s + 4), n1 = LDEB(s + 5),
                          n2 = LDEB(s + 6), n3 = LDEB(s + 7);
                    STEP((s     == last) ? 1.f : __expf(e0 - LOGC_F), pb0, pb1, s + 1);
                    STEP((s + 1 == last) ? 1.f : __expf(e1 - LOGC_F), pb1, pb0, s + 2);
                    STEP((s + 2 == last) ? 1.f : __expf(e2 - LOGC_F), pb0, pb1, s + 3);
                    STEP((s + 3 == last) ? 1.f : __expf(e3 - LOGC_F), pb1, pb0, s + 4);
                    e0 = n0; e1 = n1; e2 = n2; e3 = n3;
                }
                if (s < nbwd) { STEP((s == last) ? 1.f : __expf(e0 - LOGC_F), pb0, pb1, s + 1); ++s; }
                if (s < nbwd) { STEP((s == last) ? 1.f : __expf(e1 - LOGC_F), pb1, pb0, s + 2); ++s; }
                if (s < nbwd) { STEP((s == last) ? 1.f : __expf(e2 - LOGC_F), pb0, pb1, s + 3); }
                #undef LDEB
            }
            // v = beta_m (scaled); acc_log = acc_b
        }

        __syncthreads();
        // chain 1 publishes beta_m and acc_b
        if (chain == 1) {
            pbuf[1][0][j] = v;
            if (j == 0) accb_sh = acc_log;
        }
        __syncthreads();
        // chain 0 computes the meeting dot product and logZ
        if (chain == 0) {
            float r = v * pbuf[1][0][j];
            #pragma unroll
            for (int o = 16; o; o >>= 1)
                r += __shfl_xor_sync(0xffffffffu, r, o);
            if (lane == 0) wsum[wslot] = r;
            asm volatile("bar.sync %0, 128;" :: "r"(barid) : "memory");
            if (j == 0) {
                float dot = wsum[0] + wsum[1] + wsum[2] + wsum[3];
                g_logZ[b] = (float)((double)acc_log + (double)accb_sh
                                    + (double)(len - 1) * LOGC_D
                                    + log((double)dot));
            }
        }
        __syncthreads();
    }
    #undef STEP

    // ---- fused final reduction (last CTA) ----
    if (tid == 0) {
        __threadfence();
        unsigned int old = atomicAdd(&g_done, 1u);
        sflag = (old == NCTA - 1) ? 1 : 0;
    }
    __syncthreads();
    if (sflag) {
        __threadfence();
        shd[tid] = (double)g_logZ[tid] - (double)g_score[tid];
        __syncthreads();
        for (int o = 128; o; o >>= 1) {
            if (tid < o) shd[tid] += shd[tid + o];
            __syncthreads();
        }
        if (tid == 0) {
            out[0] = (float)(shd[0] / (double)B_DIM);
            g_done = 0;   // self-reset for graph replay
        }
    }
}

extern "C" void kernel_launch(void* const* d_in, const int* in_sizes, int n_in,
                              void* d_out, int out_size) {
    const float* emit   = (const float*)d_in[0];
    const int*   target = (const int*)d_in[1];
    const int*   mask   = (const int*)d_in[2];
    const float* trans  = (const float*)d_in[3];
    const float* strans = (const float*)d_in[4];
    const float* etrans = (const float*)d_in[5];

    scoreA1<<<NCHUNK, B_DIM>>>(emit, target, mask, trans);
    scoreA2<<<1, B_DIM>>>(target, strans, etrans);
    forward_kernel<<<NCTA, 256>>>(emit, trans, strans, etrans, (float*)d_out);
}